// round 6
// baseline (speedup 1.0000x reference)
#include <cuda_runtime.h>
#include <cuda_bf16.h>
#include <cstdint>

#define NN 20000
#define EE 640000
#define RR 65
#define FIN 128
#define HH1 64
#define HH2 32
#define BB 8192
#define KEYS (RR*NN)
#define NBLK ((KEYS + 1023) / 1024)
#define SEG1 20096               /* 157*128 padded segment rows */
#define RCP1 4224                /* 33*128 padded cols layer1 */
#define RCP2 2176                /* 17*128 padded cols layer2 */

#define OUT_RETOS  (BB*RR)
#define OUT_RETOSA (OUT_RETOS + 2*NN)
#define OUT_X2O    (OUT_RETOSA + 2*NN)

#define RCOLS1 (RR*HH1)   /* 4160 */
#define RCOLS2 (RR*HH2)   /* 2080 */

// ---------------- scratch ------------------------------------------------------
__device__ float g_h1O[NN * HH1];
__device__ float g_h1A[NN * HH1];
__device__ float g_h1Aa[NN * HH1];
__device__ float g_x2o[NN * HH2];
__device__ float g_x2oa[NN * HH2];
__device__ float g_x2oaa[NN * HH2];
__device__ int   g_cnt0[KEYS];
__device__ int   g_cnt1[KEYS];
__device__ float g_inv0[KEYS];
__device__ float g_inv1[KEYS];
__device__ __align__(16) float g_colsum[HH2];
__device__ __align__(16) float g_v[HH2];

// CSR by (etype * NN + src)
__device__ int  g_hist0[KEYS], g_hist1[KEYS];
__device__ int  g_off0[KEYS + 1], g_off1[KEYS + 1];
__device__ int  g_cur0[KEYS], g_cur1[KEYS];
__device__ int2 g_sd0[EE], g_sd1[EE];
__device__ float g_sc0[EE], g_sc1[EE];
__device__ int  g_blk0[NBLK + 1], g_blk1[NBLK + 1];

// packed bf16 hi/lo operands (segment-strided)
__device__ __nv_bfloat16 g_l1hi[2 * SEG1 * FIN], g_l1lo[2 * SEG1 * FIN];
__device__ __nv_bfloat16 g_l2hi[3 * SEG1 * HH1], g_l2lo[3 * SEG1 * HH1];
__device__ __nv_bfloat16 g_w1hi[RCP1 * FIN], g_w1lo[RCP1 * FIN];
__device__ __nv_bfloat16 g_w2hi[RCP2 * HH1], g_w2lo[RCP2 * HH1];

// ---------------- helpers ------------------------------------------------------
__device__ __forceinline__ uint32_t smem_u32(const void* p) {
    uint32_t a;
    asm("{ .reg .u64 t; cvta.to.shared.u64 t, %1; cvt.u32.u64 %0, t; }" : "=r"(a) : "l"(p));
    return a;
}
__device__ __forceinline__ void cp16(uint32_t dst, const void* src) {
    asm volatile("cp.async.cg.shared.global [%0], [%1], 16;"
                 :: "r"(dst), "l"(src) : "memory");
}
__device__ __forceinline__ void mma16816(float* d, const uint32_t* a, const uint32_t* b) {
    asm volatile("mma.sync.aligned.m16n8k16.row.col.f32.bf16.bf16.f32 "
        "{%0,%1,%2,%3}, {%4,%5,%6,%7}, {%8,%9}, {%0,%1,%2,%3};"
        : "+f"(d[0]), "+f"(d[1]), "+f"(d[2]), "+f"(d[3])
        : "r"(a[0]), "r"(a[1]), "r"(a[2]), "r"(a[3]), "r"(b[0]), "r"(b[1]));
}
#define LDSM4(R0,R1,R2,R3,addr) \
    asm volatile("ldmatrix.sync.aligned.m8n8.x4.shared.b16 {%0,%1,%2,%3}, [%4];" \
        : "=r"(R0), "=r"(R1), "=r"(R2), "=r"(R3) : "r"(addr))

struct ScatAll {
    const int*   off[3][2];
    const int2*  sd[3][2];
    const float* sc[3][2];
    float*       out[3][2];
};

// ---------------- fused GEMM + edge scatter (segmented, ldmatrix) --------------
template<int K, int H>
__global__ void __launch_bounds__(256, 2)
gemm_fused(const __nv_bfloat16* __restrict__ Ahi_g, const __nv_bfloat16* __restrict__ Alo_g,
           const __nv_bfloat16* __restrict__ Bhi_g, const __nv_bfloat16* __restrict__ Blo_g,
           ScatAll P)
{
    constexpr int KC = 32, NC = K / KC;
    constexpr int TILE_B = 128 * 80;       // 128 rows x 80B padded (40 bf16)
    extern __shared__ __align__(16) char sm[];

    const int tid = threadIdx.x;
    const int wid = tid >> 5, lane = tid & 31;
    const int gid = lane >> 2, tig = lane & 3;
    const int wm = wid & 1, wn = wid >> 1;
    const int m0 = blockIdx.x * 128;       // global packed row
    const int n0 = blockIdx.y * 128;
    const uint32_t smu = smem_u32(sm);

    float acc[4][4][4] = {};

    // per-lane ldmatrix byte offsets within a tile buffer
    uint32_t a_off[4], b_off[2];
    #pragma unroll
    for (int mt = 0; mt < 4; mt++)
        a_off[mt] = (uint32_t)((wm * 64 + mt * 16 + (lane & 15)) * 80 + ((lane & 16) ? 16 : 0));
    #pragma unroll
    for (int p = 0; p < 2; p++)
        b_off[p] = (uint32_t)((wn * 32 + p * 16 + (lane & 7) + ((lane & 16) ? 8 : 0)) * 80
                              + ((lane & 8) ? 16 : 0));

    auto load_chunk = [&](int c, int s) {
        const int koff = c * KC;
        const uint32_t st = smu + s * (4 * TILE_B);
        const __nv_bfloat16* srcs[4] = { Ahi_g, Alo_g, Bhi_g, Blo_g };
        #pragma unroll
        for (int j = 0; j < 8; j++) {
            int i = tid + j * 256;
            int t = i >> 9;
            int row = (i >> 2) & 127;
            int ch = i & 3;
            int rg = (t < 2 ? m0 : n0) + row;
            cp16(st + t * TILE_B + row * 80 + ch * 16,
                 srcs[t] + (size_t)rg * K + koff + ch * 8);
        }
        asm volatile("cp.async.commit_group;" ::: "memory");
    };

    auto compute = [&](int s) {
        const uint32_t base = smu + s * (4 * TILE_B);
        #pragma unroll
        for (int ks = 0; ks < 2; ks++) {
            const uint32_t kb = ks * 32;
            uint32_t ah[4][4], al[4][4], bh[4][2], bl[4][2];
            #pragma unroll
            for (int mt = 0; mt < 4; mt++) {
                LDSM4(ah[mt][0], ah[mt][1], ah[mt][2], ah[mt][3], base + a_off[mt] + kb);
                LDSM4(al[mt][0], al[mt][1], al[mt][2], al[mt][3], base + TILE_B + a_off[mt] + kb);
            }
            #pragma unroll
            for (int p = 0; p < 2; p++) {
                LDSM4(bh[2*p][0], bh[2*p][1], bh[2*p+1][0], bh[2*p+1][1],
                      base + 2 * TILE_B + b_off[p] + kb);
                LDSM4(bl[2*p][0], bl[2*p][1], bl[2*p+1][0], bl[2*p+1][1],
                      base + 3 * TILE_B + b_off[p] + kb);
            }
            #pragma unroll
            for (int mt = 0; mt < 4; mt++)
                #pragma unroll
                for (int nt = 0; nt < 4; nt++) {
                    mma16816(acc[mt][nt], ah[mt], bh[nt]);
                    mma16816(acc[mt][nt], ah[mt], bl[nt]);
                    mma16816(acc[mt][nt], al[mt], bh[nt]);
                }
        }
    };

    load_chunk(0, 0);
    #pragma unroll
    for (int c = 0; c < NC; c++) {
        if (c + 1 < NC) {
            load_chunk(c + 1, (c + 1) & 1);
            asm volatile("cp.async.wait_group 1;" ::: "memory");
        } else {
            asm volatile("cp.async.wait_group 0;" ::: "memory");
        }
        __syncthreads();
        compute(c & 1);
        __syncthreads();
    }

    // ---- stage tile to SMEM ----
    float* Dsm = reinterpret_cast<float*>(sm);
    #pragma unroll
    for (int mt = 0; mt < 4; mt++) {
        int r = wm * 64 + mt * 16 + gid;
        #pragma unroll
        for (int nt = 0; nt < 4; nt++) {
            int c = wn * 32 + nt * 8 + tig * 2;
            *reinterpret_cast<float2*>(Dsm + r * 132 + c) =
                make_float2(acc[mt][nt][0], acc[mt][nt][1]);
            *reinterpret_cast<float2*>(Dsm + (r + 8) * 132 + c) =
                make_float2(acc[mt][nt][2], acc[mt][nt][3]);
        }
    }
    __syncthreads();

    // ---- edge scatter from SMEM ----
    const int seg = m0 / SEG1;
    const int mloc = m0 - seg * SEG1;
    constexpr int TPE = H / 4;
    constexpr int NSUB = 256 / TPE;
    const int sub = tid / TPE, q = tid % TPE;
    const int end_src = (mloc + 128 <= NN) ? 128 : (NN - mloc);
    const int r_base = n0 / H;

    #pragma unroll
    for (int pq = 0; pq < 2; pq++) {
        float* outp = P.out[seg][pq];
        if (!outp) continue;
        const int* off = P.off[seg][pq];
        const int2* sd = P.sd[seg][pq];
        const float* sc = P.sc[seg][pq];
        #pragma unroll
        for (int ri = 0; ri < 128 / H; ri++) {
            int r = r_base + ri;
            if (r >= RR) break;
            int kb = r * NN + mloc;
            int b0 = off[kb], b1 = off[kb + end_src];
            for (int e = b0 + sub; e < b1; e += NSUB) {
                int2 sdv = sd[e];
                float scale = sc[e];
                const float* p = Dsm + (sdv.x - mloc) * 132 + ri * H + q * 4;
                float4 v = *reinterpret_cast<const float4*>(p);
                float4 w = make_float4(v.x * scale, v.y * scale, v.z * scale, v.w * scale);
                atomicAdd(reinterpret_cast<float4*>(outp + (size_t)sdv.y * H + q * 4), w);
            }
        }
    }
}

// ---------------- CSR build ----------------------------------------------------
__global__ void zero_k() {
    int i = blockIdx.x * blockDim.x + threadIdx.x;
    if (i < KEYS) { g_cnt0[i] = 0; g_cnt1[i] = 0; g_hist0[i] = 0; g_hist1[i] = 0; }
    if (i < HH2) g_colsum[i] = 0.f;
}
__global__ void count_k(const int* __restrict__ ei, const int* __restrict__ et0,
                        const int* __restrict__ et1) {
    int e = blockIdx.x * blockDim.x + threadIdx.x;
    if (e >= EE) return;
    int s = ei[e], d = ei[EE + e];
    int r0 = et0[e], r1 = et1[e];
    atomicAdd(&g_cnt0[r0 * NN + d], 1);
    atomicAdd(&g_cnt1[r1 * NN + d], 1);
    atomicAdd(&g_hist0[r0 * NN + s], 1);
    atomicAdd(&g_hist1[r1 * NN + s], 1);
}
__global__ void inv_k() {
    int i = blockIdx.x * blockDim.x + threadIdx.x;
    if (i >= KEYS) return;
    g_inv0[i] = 1.f / (float)max(g_cnt0[i], 1);
    g_inv1[i] = 1.f / (float)max(g_cnt1[i], 1);
}
__global__ void scan1_k() {
    __shared__ int smi[1024];
    const int* hist = blockIdx.y ? g_hist1 : g_hist0;
    int* off = blockIdx.y ? g_off1 : g_off0;
    int* blk = blockIdx.y ? g_blk1 : g_blk0;
    int g = blockIdx.x * 1024 + threadIdx.x;
    int v = (g < KEYS) ? hist[g] : 0;
    smi[threadIdx.x] = v;
    __syncthreads();
    for (int o = 1; o < 1024; o <<= 1) {
        int t = (threadIdx.x >= o) ? smi[threadIdx.x - o] : 0;
        __syncthreads();
        smi[threadIdx.x] += t;
        __syncthreads();
    }
    if (g < KEYS) off[g] = smi[threadIdx.x] - v;
    if (threadIdx.x == 1023) blk[blockIdx.x] = smi[1023];
}
__global__ void scan2_k() {
    __shared__ int smi[1024];
    __shared__ int run;
    int* blk = blockIdx.x ? g_blk1 : g_blk0;
    if (threadIdx.x == 0) run = 0;
    __syncthreads();
    for (int base = 0; base < NBLK; base += 1024) {
        int i = base + threadIdx.x;
        int v = (i < NBLK) ? blk[i] : 0;
        smi[threadIdx.x] = v;
        __syncthreads();
        for (int o = 1; o < 1024; o <<= 1) {
            int t = (threadIdx.x >= o) ? smi[threadIdx.x - o] : 0;
            __syncthreads();
            smi[threadIdx.x] += t;
            __syncthreads();
        }
        int r = run;
        int excl = smi[threadIdx.x] - v + r;
        if (i < NBLK) blk[i] = excl;
        __syncthreads();
        if (threadIdx.x == 1023) run = r + smi[1023];
        __syncthreads();
    }
}
__global__ void scan3_k() {
    int* off = blockIdx.y ? g_off1 : g_off0;
    const int* blk = blockIdx.y ? g_blk1 : g_blk0;
    int* cur = blockIdx.y ? g_cur1 : g_cur0;
    int g = blockIdx.x * 1024 + threadIdx.x;
    if (g < KEYS) {
        int v = off[g] + blk[blockIdx.x];
        off[g] = v;
        cur[g] = v;
    }
    if (g == 0) off[KEYS] = EE;
}
__global__ void fill_k(const int* __restrict__ ei, const int* __restrict__ et0,
                       const int* __restrict__ et1) {
    int e = blockIdx.x * blockDim.x + threadIdx.x;
    if (e >= EE) return;
    int s = ei[e], d = ei[EE + e];
    {
        int r = et0[e];
        int p = atomicAdd(&g_cur0[r * NN + s], 1);
        g_sd0[p] = make_int2(s, d);
        g_sc0[p] = g_inv0[r * NN + d];
    }
    {
        int r = et1[e];
        int p = atomicAdd(&g_cur1[r * NN + s], 1);
        g_sd1[p] = make_int2(s, d);
        g_sc1[p] = g_inv1[r * NN + d];
    }
}

// ---------------- conversion kernels -------------------------------------------
__global__ void convX2_k(const float* __restrict__ x_o, const float* __restrict__ x_a) {
    int i = blockIdx.x * blockDim.x + threadIdx.x;
    if (i >= 2 * SEG1 * FIN) return;
    int seg = i / (SEG1 * FIN);
    int j = i - seg * (SEG1 * FIN);
    int row = j / FIN, col = j - row * FIN;
    float v = 0.f;
    if (row < NN) v = (seg ? x_a : x_o)[row * FIN + col];
    __nv_bfloat16 h = __float2bfloat16_rn(v);
    g_l1hi[i] = h;
    g_l1lo[i] = __float2bfloat16_rn(v - __bfloat162float(h));
}
template<int K, int H, int RCOLS, int RCP>
__global__ void convW_k(const float* __restrict__ W, __nv_bfloat16* __restrict__ hi,
                        __nv_bfloat16* __restrict__ lo) {
    int i = blockIdx.x * blockDim.x + threadIdx.x;
    if (i >= RCP * K) return;
    int c = i / K, k = i - c * K;
    float v = 0.f;
    if (c < RCOLS) v = W[(size_t)(c / H) * (K * H) + (size_t)k * H + (c % H)];
    __nv_bfloat16 h = __float2bfloat16_rn(v);
    hi[i] = h;
    lo[i] = __float2bfloat16_rn(v - __bfloat162float(h));
}
__global__ void relu_conv_k() {
    int i = blockIdx.x * blockDim.x + threadIdx.x;
    if (i >= 3 * SEG1 * HH1) return;
    int seg = i / (SEG1 * HH1);
    int j = i - seg * (SEG1 * HH1);
    int row = j / HH1, col = j - row * HH1;
    float v = 0.f;
    if (row < NN) {
        float* arr = (seg == 0) ? g_h1O : (seg == 1) ? g_h1A : g_h1Aa;
        v = fmaxf(arr[row * HH1 + col], 0.f);
        arr[row * HH1 + col] = v;
    }
    __nv_bfloat16 h = __float2bfloat16_rn(v);
    g_l2hi[i] = h;
    g_l2lo[i] = __float2bfloat16_rn(v - __bfloat162float(h));
}

// ---------------- root GEMM (SIMT, small) --------------------------------------
template<int K, int H>
__global__ void __launch_bounds__((H/4)*16)
gemm_rel(const float* __restrict__ X, const float* __restrict__ Wm,
         const float* __restrict__ bias, float* __restrict__ Y,
         float* __restrict__ Ydup, int ldY, int nrows)
{
    constexpr int TM = 64, KC = 64;
    constexpr int DX = H / 4;
    constexpr int NT = DX * 16;
    __shared__ __align__(16) float At[KC][TM + 4];
    __shared__ __align__(16) float Bs[KC][H];
    int row0 = blockIdx.x * TM;
    int tx = threadIdx.x, ty = threadIdx.y;
    int tid = ty * DX + tx;
    int c0 = tx * 4, r0 = ty * 4;
    float acc[4][4] = {};
    for (int kc = 0; kc < K; kc += KC) {
        for (int c = tid; c < TM * (KC / 4); c += NT) {
            int row = c / (KC / 4), kq = c % (KC / 4);
            float4 v = make_float4(0.f, 0.f, 0.f, 0.f);
            if (row0 + row < nrows)
                v = *reinterpret_cast<const float4*>(X + (size_t)(row0 + row) * K + kc + kq * 4);
            At[kq * 4 + 0][row] = v.x; At[kq * 4 + 1][row] = v.y;
            At[kq * 4 + 2][row] = v.z; At[kq * 4 + 3][row] = v.w;
        }
        for (int c = tid; c < KC * H / 4; c += NT)
            reinterpret_cast<float4*>(&Bs[0][0])[c] =
                reinterpret_cast<const float4*>(Wm + (size_t)kc * H)[c];
        __syncthreads();
        #pragma unroll 8
        for (int k = 0; k < KC; k++) {
            float4 a = *reinterpret_cast<const float4*>(&At[k][r0]);
            float4 b = *reinterpret_cast<const float4*>(&Bs[k][c0]);
            acc[0][0] += a.x*b.x; acc[0][1] += a.x*b.y; acc[0][2] += a.x*b.z; acc[0][3] += a.x*b.w;
            acc[1][0] += a.y*b.x; acc[1][1] += a.y*b.y; acc[1][2] += a.y*b.z; acc[1][3] += a.y*b.w;
            acc[2][0] += a.z*b.x; acc[2][1] += a.z*b.y; acc[2][2] += a.z*b.z; acc[2][3] += a.z*b.w;
            acc[3][0] += a.w*b.x; acc[3][1] += a.w*b.y; acc[3][2] += a.w*b.z; acc[3][3] += a.w*b.w;
        }
        __syncthreads();
    }
    float4 bv = make_float4(0.f, 0.f, 0.f, 0.f);
    if (bias) bv = *reinterpret_cast<const float4*>(bias + c0);
    #pragma unroll
    for (int i = 0; i < 4; i++) {
        int row = row0 + r0 + i;
        if (row < nrows) {
            float4 o = make_float4(acc[i][0] + bv.x, acc[i][1] + bv.y,
                                   acc[i][2] + bv.z, acc[i][3] + bv.w);
            *reinterpret_cast<float4*>(Y + (size_t)row * ldY + c0) = o;
            if (Ydup) *reinterpret_cast<float4*>(Ydup + (size_t)row * ldY + c0) = o;
        }
    }
}

// ---------------- readout / discriminator --------------------------------------
__global__ void colsum_k() {
    __shared__ float smf[256];
    int col = threadIdx.x & 31, grp = threadIdx.x >> 5;
    float s = 0.f;
    for (int n = blockIdx.x * 8 + grp; n < NN; n += gridDim.x * 8)
        s += g_x2o[n * HH2 + col];
    smf[threadIdx.x] = s;
    __syncthreads();
    if (threadIdx.x < 32) {
        float t = 0.f;
        #pragma unroll
        for (int g2 = 0; g2 < 8; g2++) t += smf[g2 * 32 + threadIdx.x];
        atomicAdd(&g_colsum[threadIdx.x], t);
    }
}
__global__ void finalize_k(const float* __restrict__ discW) {
    __shared__ float c[HH2];
    int t = threadIdx.x;
    float m = g_colsum[t] / (float)NN;
    c[t] = 1.f / (1.f + expf(-m));
    __syncwarp();
    float v = 0.f;
    #pragma unroll
    for (int k = 0; k < HH2; k++) v += discW[t * HH2 + k] * c[k];
    g_v[t] = v;
}
__global__ void ret_k(const float* __restrict__ dbp, float* __restrict__ out) {
    int n = blockIdx.x * blockDim.x + threadIdx.x;
    if (n >= NN) return;
    float db = dbp[0];
    float d0 = 0.f, d1 = 0.f, d2 = 0.f;
    float* xo_out = out + OUT_X2O + (size_t)n * HH2;
    #pragma unroll
    for (int k = 0; k < HH2; k += 4) {
        float4 v4 = *reinterpret_cast<const float4*>(&g_v[k]);
        float4 a  = *reinterpret_cast<const float4*>(&g_x2o[n * HH2 + k]);
        float4 b  = *reinterpret_cast<const float4*>(&g_x2oa[n * HH2 + k]);
        float4 c  = *reinterpret_cast<const float4*>(&g_x2oaa[n * HH2 + k]);
        d0 += a.x*v4.x + a.y*v4.y + a.z*v4.z + a.w*v4.w;
        d1 += b.x*v4.x + b.y*v4.y + b.z*v4.z + b.w*v4.w;
        d2 += c.x*v4.x + c.y*v4.y + c.z*v4.z + c.w*v4.w;
        *reinterpret_cast<float4*>(&xo_out[k]) = a;
    }
    out[OUT_RETOS  + 2 * n]     = d0 + db;
    out[OUT_RETOS  + 2 * n + 1] = d1 + db;
    out[OUT_RETOSA + 2 * n]     = d0 + db;
    out[OUT_RETOSA + 2 * n + 1] = d2 + db;
}
__global__ void cls_k(const int* __restrict__ idx, const float* __restrict__ f1,
                      const float* __restrict__ clsW, const float* __restrict__ clsB,
                      const float* __restrict__ attt, float* __restrict__ out)
{
    __shared__ float z[448];
    int b = blockIdx.x, t = threadIdx.x;
    int i0 = idx[b], i1 = idx[BB + b];
    float a0 = attt[0], a1 = attt[1];
    for (int k = t; k < 448; k += 128) {
        float val;
        if      (k < 64)  val = a0 * g_h1O[(size_t)i0 * 64 + k];
        else if (k < 96)  val = a1 * g_x2o[(size_t)i0 * 32 + (k - 64)];
        else if (k < 224) val = f1[(size_t)i0 * 128 + (k - 96)];
        else if (k < 288) val = a0 * g_h1O[(size_t)i1 * 64 + (k - 224)];
        else if (k < 320) val = a1 * g_x2o[(size_t)i1 * 32 + (k - 288)];
        else              val = f1[(size_t)i1 * 128 + (k - 320)];
        z[k] = val;
    }
    __syncthreads();
    if (t < RR) {
        float acc = clsB[t];
        #pragma unroll 4
        for (int k = 0; k < 448; k++) acc += z[k] * clsW[k * RR + t];
        out[(size_t)b * RR + t] = acc;
    }
}

// ---------------- launcher ------------------------------------------------------
extern "C" void kernel_launch(void* const* d_in, const int* in_sizes, int n_in,
                              void* d_out, int out_size)
{
    (void)in_sizes; (void)n_in; (void)out_size;
    const float* x_o   = (const float*)d_in[0];
    const float* x_a   = (const float*)d_in[1];
    const float* f1    = (const float*)d_in[2];
    const float* W1    = (const float*)d_in[3];
    const float* root1 = (const float*)d_in[4];
    const float* b1    = (const float*)d_in[5];
    const float* W2    = (const float*)d_in[6];
    const float* root2 = (const float*)d_in[7];
    const float* b2    = (const float*)d_in[8];
    const float* attt  = (const float*)d_in[9];
    const float* discW = (const float*)d_in[10];
    const float* discb = (const float*)d_in[11];
    const float* clsW  = (const float*)d_in[12];
    const float* clsb  = (const float*)d_in[13];
    const int*   ei    = (const int*)d_in[14];
    const int*   et0   = (const int*)d_in[15];
    const int*   et1   = (const int*)d_in[16];
    const int*   idx   = (const int*)d_in[17];
    float* out = (float*)d_out;

    float *h1O, *h1A, *h1Aa, *x2o, *x2oa, *x2oaa;
    cudaGetSymbolAddress((void**)&h1O,   g_h1O);
    cudaGetSymbolAddress((void**)&h1A,   g_h1A);
    cudaGetSymbolAddress((void**)&h1Aa,  g_h1Aa);
    cudaGetSymbolAddress((void**)&x2o,   g_x2o);
    cudaGetSymbolAddress((void**)&x2oa,  g_x2oa);
    cudaGetSymbolAddress((void**)&x2oaa, g_x2oaa);

    int *off0, *off1;
    int2 *sd0, *sd1;
    float *sc0, *sc1;
    cudaGetSymbolAddress((void**)&off0, g_off0); cudaGetSymbolAddress((void**)&off1, g_off1);
    cudaGetSymbolAddress((void**)&sd0, g_sd0);   cudaGetSymbolAddress((void**)&sd1, g_sd1);
    cudaGetSymbolAddress((void**)&sc0, g_sc0);   cudaGetSymbolAddress((void**)&sc1, g_sc1);

    __nv_bfloat16 *l1hi, *l1lo, *l2hi, *l2lo, *w1hi, *w1lo, *w2hi, *w2lo;
    cudaGetSymbolAddress((void**)&l1hi, g_l1hi); cudaGetSymbolAddress((void**)&l1lo, g_l1lo);
    cudaGetSymbolAddress((void**)&l2hi, g_l2hi); cudaGetSymbolAddress((void**)&l2lo, g_l2lo);
    cudaGetSymbolAddress((void**)&w1hi, g_w1hi); cudaGetSymbolAddress((void**)&w1lo, g_w1lo);
    cudaGetSymbolAddress((void**)&w2hi, g_w2hi); cudaGetSymbolAddress((void**)&w2lo, g_w2lo);

    const int SMP = 2 * 4 * 128 * 80;   // 81920
    cudaFuncSetAttribute(gemm_fused<FIN, HH1>,
                         cudaFuncAttributeMaxDynamicSharedMemorySize, SMP);
    cudaFuncSetAttribute(gemm_fused<HH1, HH2>,
                         cudaFuncAttributeMaxDynamicSharedMemorySize, SMP);

    const int tK = (KEYS + 255) / 256;
    const int gx = (NN + 63) / 64;
    dim3 gb1(16, 16), gb2(8, 16);

    // ---- CSR build ----
    zero_k<<<tK, 256>>>();
    count_k<<<(EE + 255) / 256, 256>>>(ei, et0, et1);
    inv_k<<<tK, 256>>>();
    scan1_k<<<dim3(NBLK, 2), 1024>>>();
    scan2_k<<<2, 1024>>>();
    scan3_k<<<dim3(NBLK, 2), 1024>>>();
    fill_k<<<(EE + 255) / 256, 256>>>(ei, et0, et1);

    // ---- conversions ----
    convX2_k<<<(2 * SEG1 * FIN + 255) / 256, 256>>>(x_o, x_a);
    convW_k<FIN, HH1, RCOLS1, RCP1><<<(RCP1 * FIN + 255) / 256, 256>>>(W1, w1hi, w1lo);
    convW_k<HH1, HH2, RCOLS2, RCP2><<<(RCP2 * HH1 + 255) / 256, 256>>>(W2, w2hi, w2lo);

    // ---- layer 1: root inits then one fused launch over both segments ----
    gemm_rel<FIN, HH1><<<gx, gb1>>>(x_o, root1, b1, h1O, h1Aa, HH1, NN);
    gemm_rel<FIN, HH1><<<gx, gb1>>>(x_a, root1, b1, h1A, nullptr, HH1, NN);
    {
        ScatAll P = {};
        P.off[0][0] = off0; P.sd[0][0] = sd0; P.sc[0][0] = sc0; P.out[0][0] = h1O;
        P.off[0][1] = off1; P.sd[0][1] = sd1; P.sc[0][1] = sc1; P.out[0][1] = h1Aa;
        P.off[1][0] = off0; P.sd[1][0] = sd0; P.sc[1][0] = sc0; P.out[1][0] = h1A;
        gemm_fused<FIN, HH1><<<dim3(2 * 157, RCP1 / 128), 256, SMP>>>(
            l1hi, l1lo, w1hi, w1lo, P);
    }

    relu_conv_k<<<(3 * SEG1 * HH1 + 255) / 256, 256>>>();

    // ---- layer 2: root inits then one fused launch over three segments ----
    gemm_rel<HH1, HH2><<<gx, gb2>>>(h1O, root2, b2, x2o, nullptr, HH2, NN);
    gemm_rel<HH1, HH2><<<gx, gb2>>>(h1A, root2, b2, x2oa, nullptr, HH2, NN);
    gemm_rel<HH1, HH2><<<gx, gb2>>>(h1Aa, root2, b2, x2oaa, nullptr, HH2, NN);
    {
        ScatAll P = {};
        P.off[0][0] = off0; P.sd[0][0] = sd0; P.sc[0][0] = sc0; P.out[0][0] = x2o;
        P.off[1][0] = off0; P.sd[1][0] = sd0; P.sc[1][0] = sc0; P.out[1][0] = x2oa;
        P.off[2][0] = off1; P.sd[2][0] = sd1; P.sc[2][0] = sc1; P.out[2][0] = x2oaa;
        gemm_fused<HH1, HH2><<<dim3(3 * 157, RCP2 / 128), 256, SMP>>>(
            l2hi, l2lo, w2hi, w2lo, P);
    }

    // ---- readout / outputs ----
    colsum_k<<<80, 256>>>();
    finalize_k<<<1, 32>>>(discW);
    ret_k<<<(NN + 127) / 128, 128>>>(discb, out);
    cls_k<<<BB, 128>>>(idx, f1, clsW, clsb, attt, out);
}

// round 7
// speedup vs baseline: 1.0626x; 1.0626x over previous
#include <cuda_runtime.h>
#include <cuda_bf16.h>
#include <cstdint>

#define NN 20000
#define EE 640000
#define RR 65
#define FIN 128
#define HH1 64
#define HH2 32
#define BB 8192
#define SEG1 20096               /* 157*128 padded segment rows */
#define NTILE 157
#define NB (RR * NTILE)          /* 10205 tile buckets */
#define KEYS (RR * NN)
#define RCP1 4224                /* 66*64: rel 65 = root1 */
#define RCP2 2176                /* 68*32: rel 65 = root2, 66-67 zero */

#define OUT_RETOS  (BB*RR)
#define OUT_RETOSA (OUT_RETOS + 2*NN)
#define OUT_X2O    (OUT_RETOSA + 2*NN)

// ---------------- scratch ------------------------------------------------------
__device__ float g_h1O[NN * HH1];
__device__ float g_h1A[NN * HH1];
__device__ float g_h1Aa[NN * HH1];
__device__ float g_x2o[NN * HH2];
__device__ float g_x2oa[NN * HH2];
__device__ float g_x2oaa[NN * HH2];
__device__ int   g_cnt0[KEYS];
__device__ int   g_cnt1[KEYS];
__device__ __align__(16) float g_colsum[HH2];
__device__ __align__(16) float g_v[HH2];

// tile-bucket CSR: key = r*NTILE + (src>>7)
__device__ int  g_bh0[NB], g_bh1[NB];
__device__ int  g_boff0[NB + 1], g_boff1[NB + 1];
__device__ int  g_bcur0[NB], g_bcur1[NB];
__device__ int2 g_sd0[EE], g_sd1[EE];
__device__ float g_sc0[EE], g_sc1[EE];

// packed bf16 hi/lo operands (segment-strided)
__device__ __nv_bfloat16 g_l1hi[2 * SEG1 * FIN], g_l1lo[2 * SEG1 * FIN];
__device__ __nv_bfloat16 g_l2hi[3 * SEG1 * HH1], g_l2lo[3 * SEG1 * HH1];
__device__ __nv_bfloat16 g_w1hi[RCP1 * FIN], g_w1lo[RCP1 * FIN];
__device__ __nv_bfloat16 g_w2hi[RCP2 * HH1], g_w2lo[RCP2 * HH1];

// ---------------- helpers ------------------------------------------------------
__device__ __forceinline__ uint32_t smem_u32(const void* p) {
    uint32_t a;
    asm("{ .reg .u64 t; cvta.to.shared.u64 t, %1; cvt.u32.u64 %0, t; }" : "=r"(a) : "l"(p));
    return a;
}
__device__ __forceinline__ void cp16(uint32_t dst, const void* src) {
    asm volatile("cp.async.cg.shared.global [%0], [%1], 16;"
                 :: "r"(dst), "l"(src) : "memory");
}
__device__ __forceinline__ void mma16816(float* d, const uint32_t* a, const uint32_t* b) {
    asm volatile("mma.sync.aligned.m16n8k16.row.col.f32.bf16.bf16.f32 "
        "{%0,%1,%2,%3}, {%4,%5,%6,%7}, {%8,%9}, {%0,%1,%2,%3};"
        : "+f"(d[0]), "+f"(d[1]), "+f"(d[2]), "+f"(d[3])
        : "r"(a[0]), "r"(a[1]), "r"(a[2]), "r"(a[3]), "r"(b[0]), "r"(b[1]));
}
#define LDSM4(R0,R1,R2,R3,addr) \
    asm volatile("ldmatrix.sync.aligned.m8n8.x4.shared.b16 {%0,%1,%2,%3}, [%4];" \
        : "=r"(R0), "=r"(R1), "=r"(R2), "=r"(R3) : "r"(addr))

struct ScatAll {
    const int*   off[3][2];
    const int2*  sd[3][2];
    const float* sc[3][2];
    float*       out[3][2];
};

// ---------------- fused GEMM + scatter + root (segmented) ----------------------
template<int K, int H>
__global__ void __launch_bounds__(256, 2)
gemm_fused(const __nv_bfloat16* __restrict__ Ahi_g, const __nv_bfloat16* __restrict__ Alo_g,
           const __nv_bfloat16* __restrict__ Bhi_g, const __nv_bfloat16* __restrict__ Blo_g,
           ScatAll P)
{
    constexpr int KC = 32, NC = K / KC;
    constexpr int TILE_B = 128 * 80;       // 128 rows x 80B padded (40 bf16)
    extern __shared__ __align__(16) char sm[];

    const int tid = threadIdx.x;
    const int wid = tid >> 5, lane = tid & 31;
    const int gid = lane >> 2, tig = lane & 3;
    const int wm = wid & 1, wn = wid >> 1;
    const int m0 = blockIdx.x * 128;       // global packed row
    const int n0 = blockIdx.y * 128;
    const uint32_t smu = smem_u32(sm);

    float acc[4][4][4] = {};

    uint32_t a_off[4], b_off[2];
    #pragma unroll
    for (int mt = 0; mt < 4; mt++)
        a_off[mt] = (uint32_t)((wm * 64 + mt * 16 + (lane & 15)) * 80 + ((lane & 16) ? 16 : 0));
    #pragma unroll
    for (int p = 0; p < 2; p++)
        b_off[p] = (uint32_t)((wn * 32 + p * 16 + (lane & 7) + ((lane & 16) ? 8 : 0)) * 80
                              + ((lane & 8) ? 16 : 0));

    auto load_chunk = [&](int c, int s) {
        const int koff = c * KC;
        const uint32_t st = smu + s * (4 * TILE_B);
        const __nv_bfloat16* srcs[4] = { Ahi_g, Alo_g, Bhi_g, Blo_g };
        #pragma unroll
        for (int j = 0; j < 8; j++) {
            int i = tid + j * 256;
            int t = i >> 9;
            int row = (i >> 2) & 127;
            int ch = i & 3;
            int rg = (t < 2 ? m0 : n0) + row;
            cp16(st + t * TILE_B + row * 80 + ch * 16,
                 srcs[t] + (size_t)rg * K + koff + ch * 8);
        }
        asm volatile("cp.async.commit_group;" ::: "memory");
    };

    auto compute = [&](int s) {
        const uint32_t base = smu + s * (4 * TILE_B);
        #pragma unroll
        for (int ks = 0; ks < 2; ks++) {
            const uint32_t kb = ks * 32;
            uint32_t ah[4][4], al[4][4], bh[4][2], bl[4][2];
            #pragma unroll
            for (int mt = 0; mt < 4; mt++) {
                LDSM4(ah[mt][0], ah[mt][1], ah[mt][2], ah[mt][3], base + a_off[mt] + kb);
                LDSM4(al[mt][0], al[mt][1], al[mt][2], al[mt][3], base + TILE_B + a_off[mt] + kb);
            }
            #pragma unroll
            for (int p = 0; p < 2; p++) {
                LDSM4(bh[2*p][0], bh[2*p][1], bh[2*p+1][0], bh[2*p+1][1],
                      base + 2 * TILE_B + b_off[p] + kb);
                LDSM4(bl[2*p][0], bl[2*p][1], bl[2*p+1][0], bl[2*p+1][1],
                      base + 3 * TILE_B + b_off[p] + kb);
            }
            #pragma unroll
            for (int mt = 0; mt < 4; mt++)
                #pragma unroll
                for (int nt = 0; nt < 4; nt++) {
                    mma16816(acc[mt][nt], ah[mt], bh[nt]);
                    mma16816(acc[mt][nt], ah[mt], bl[nt]);
                    mma16816(acc[mt][nt], al[mt], bh[nt]);
                }
        }
    };

    load_chunk(0, 0);
    #pragma unroll
    for (int c = 0; c < NC; c++) {
        if (c + 1 < NC) {
            load_chunk(c + 1, (c + 1) & 1);
            asm volatile("cp.async.wait_group 1;" ::: "memory");
        } else {
            asm volatile("cp.async.wait_group 0;" ::: "memory");
        }
        __syncthreads();
        compute(c & 1);
        __syncthreads();
    }

    // ---- stage tile to SMEM ----
    float* Dsm = reinterpret_cast<float*>(sm);
    #pragma unroll
    for (int mt = 0; mt < 4; mt++) {
        int r = wm * 64 + mt * 16 + gid;
        #pragma unroll
        for (int nt = 0; nt < 4; nt++) {
            int c = wn * 32 + nt * 8 + tig * 2;
            *reinterpret_cast<float2*>(Dsm + r * 132 + c) =
                make_float2(acc[mt][nt][0], acc[mt][nt][1]);
            *reinterpret_cast<float2*>(Dsm + (r + 8) * 132 + c) =
                make_float2(acc[mt][nt][2], acc[mt][nt][3]);
        }
    }
    __syncthreads();

    // ---- scatter: CSR edges for real relations, dense add for phantom root ----
    const int seg = m0 / SEG1;
    const int mloc = m0 - seg * SEG1;
    const int tile = mloc >> 7;
    constexpr int TPE = H / 4;
    constexpr int NSUB = 256 / TPE;
    const int sub = tid / TPE, q = tid % TPE;
    const int end_src = (mloc + 128 <= NN) ? 128 : (NN - mloc);
    const int r_base = n0 / H;

    #pragma unroll
    for (int pq = 0; pq < 2; pq++) {
        float* outp = P.out[seg][pq];
        if (!outp) continue;
        const int* off = P.off[seg][pq];
        const int2* sd = P.sd[seg][pq];
        const float* sc = P.sc[seg][pq];
        #pragma unroll
        for (int ri = 0; ri < 128 / H; ri++) {
            int r = r_base + ri;
            if (r < RR) {
                int b = r * NTILE + tile;
                int e0 = off[b], e1 = off[b + 1];
                for (int e = e0 + sub; e < e1; e += NSUB) {
                    int2 sdv = sd[e];
                    float scale = sc[e];
                    const float* p = Dsm + (sdv.x - mloc) * 132 + ri * H + q * 4;
                    float4 v = *reinterpret_cast<const float4*>(p);
                    float4 w = make_float4(v.x * scale, v.y * scale, v.z * scale, v.w * scale);
                    atomicAdd(reinterpret_cast<float4*>(outp + (size_t)sdv.y * H + q * 4), w);
                }
            } else if (r == RR) {                  // phantom root relation
                for (int row = sub; row < end_src; row += NSUB) {
                    const float* p = Dsm + row * 132 + ri * H + q * 4;
                    float4 v = *reinterpret_cast<const float4*>(p);
                    atomicAdd(reinterpret_cast<float4*>(outp + (size_t)(mloc + row) * H + q * 4), v);
                }
            }
        }
    }
}

// ---------------- CSR build (tile buckets) -------------------------------------
__global__ void init_k(const float* __restrict__ b1) {
    int i = blockIdx.x * blockDim.x + threadIdx.x;
    if (i < KEYS) { g_cnt0[i] = 0; g_cnt1[i] = 0; }
    if (i < NB) { g_bh0[i] = 0; g_bh1[i] = 0; }
    if (i < HH2) g_colsum[i] = 0.f;
    if (i < 3 * NN * HH1) {
        int seg = i / (NN * HH1);
        int j = i - seg * (NN * HH1);
        float v = b1[j & (HH1 - 1)];
        ((seg == 0) ? g_h1O : (seg == 1) ? g_h1A : g_h1Aa)[j] = v;
    }
}
__global__ void count_k(const int* __restrict__ ei, const int* __restrict__ et0,
                        const int* __restrict__ et1) {
    int e = blockIdx.x * blockDim.x + threadIdx.x;
    if (e >= EE) return;
    int s = ei[e], d = ei[EE + e];
    int r0 = et0[e], r1 = et1[e];
    atomicAdd(&g_cnt0[r0 * NN + d], 1);
    atomicAdd(&g_cnt1[r1 * NN + d], 1);
    atomicAdd(&g_bh0[r0 * NTILE + (s >> 7)], 1);
    atomicAdd(&g_bh1[r1 * NTILE + (s >> 7)], 1);
}
__global__ void bscan_k() {
    __shared__ int smi[1024];
    __shared__ int run;
    const int* hist = blockIdx.x ? g_bh1 : g_bh0;
    int* off = blockIdx.x ? g_boff1 : g_boff0;
    int* cur = blockIdx.x ? g_bcur1 : g_bcur0;
    int t = threadIdx.x;
    if (t == 0) run = 0;
    __syncthreads();
    for (int base = 0; base < NB; base += 1024) {
        int i = base + t;
        int v = (i < NB) ? hist[i] : 0;
        smi[t] = v;
        __syncthreads();
        for (int o = 1; o < 1024; o <<= 1) {
            int x = (t >= o) ? smi[t - o] : 0;
            __syncthreads();
            smi[t] += x;
            __syncthreads();
        }
        int r = run;
        if (i < NB) { int excl = smi[t] - v + r; off[i] = excl; cur[i] = excl; }
        __syncthreads();
        if (t == 1023) run = r + smi[1023];
        __syncthreads();
    }
    if (t == 0) off[NB] = EE;
}
__global__ void bfill_k(const int* __restrict__ ei, const int* __restrict__ et0,
                        const int* __restrict__ et1) {
    int e = blockIdx.x * blockDim.x + threadIdx.x;
    if (e >= EE) return;
    int s = ei[e], d = ei[EE + e];
    {
        int r = et0[e];
        int p = atomicAdd(&g_bcur0[r * NTILE + (s >> 7)], 1);
        g_sd0[p] = make_int2(s, d);
        g_sc0[p] = 1.f / (float)max(g_cnt0[r * NN + d], 1);
    }
    {
        int r = et1[e];
        int p = atomicAdd(&g_bcur1[r * NTILE + (s >> 7)], 1);
        g_sd1[p] = make_int2(s, d);
        g_sc1[p] = 1.f / (float)max(g_cnt1[r * NN + d], 1);
    }
}

// ---------------- conversion kernels -------------------------------------------
__global__ void convX2_k(const float* __restrict__ x_o, const float* __restrict__ x_a) {
    int i = blockIdx.x * blockDim.x + threadIdx.x;
    if (i >= 2 * SEG1 * FIN) return;
    int seg = i / (SEG1 * FIN);
    int j = i - seg * (SEG1 * FIN);
    int row = j / FIN, col = j - row * FIN;
    float v = 0.f;
    if (row < NN) v = (seg ? x_a : x_o)[row * FIN + col];
    __nv_bfloat16 h = __float2bfloat16_rn(v);
    g_l1hi[i] = h;
    g_l1lo[i] = __float2bfloat16_rn(v - __bfloat162float(h));
}
template<int K, int H, int RCP>
__global__ void convW_k(const float* __restrict__ W, const float* __restrict__ root,
                        __nv_bfloat16* __restrict__ hi, __nv_bfloat16* __restrict__ lo) {
    int i = blockIdx.x * blockDim.x + threadIdx.x;
    if (i >= RCP * K) return;
    int c = i / K, k = i - c * K;
    int r = c / H;
    float v = 0.f;
    if (r < RR)       v = W[(size_t)r * (K * H) + (size_t)k * H + (c % H)];
    else if (r == RR) v = root[(size_t)k * H + (c % H)];
    __nv_bfloat16 h = __float2bfloat16_rn(v);
    hi[i] = h;
    lo[i] = __float2bfloat16_rn(v - __bfloat162float(h));
}
__global__ void relu_conv_k(const float* __restrict__ b2) {
    int i = blockIdx.x * blockDim.x + threadIdx.x;
    if (i < 3 * SEG1 * HH1) {
        int seg = i / (SEG1 * HH1);
        int j = i - seg * (SEG1 * HH1);
        int row = j / HH1, col = j - row * HH1;
        float v = 0.f;
        if (row < NN) {
            float* arr = (seg == 0) ? g_h1O : (seg == 1) ? g_h1A : g_h1Aa;
            v = fmaxf(arr[row * HH1 + col], 0.f);
            arr[row * HH1 + col] = v;
        }
        __nv_bfloat16 h = __float2bfloat16_rn(v);
        g_l2hi[i] = h;
        g_l2lo[i] = __float2bfloat16_rn(v - __bfloat162float(h));
    }
    if (i < 3 * NN * HH2) {
        int seg = i / (NN * HH2);
        int j = i - seg * (NN * HH2);
        ((seg == 0) ? g_x2o : (seg == 1) ? g_x2oa : g_x2oaa)[j] = b2[j & (HH2 - 1)];
    }
}

// ---------------- readout / discriminator --------------------------------------
__global__ void colsum_k() {
    __shared__ float smf[256];
    int col = threadIdx.x & 31, grp = threadIdx.x >> 5;
    float s = 0.f;
    for (int n = blockIdx.x * 8 + grp; n < NN; n += gridDim.x * 8)
        s += g_x2o[n * HH2 + col];
    smf[threadIdx.x] = s;
    __syncthreads();
    if (threadIdx.x < 32) {
        float t = 0.f;
        #pragma unroll
        for (int g2 = 0; g2 < 8; g2++) t += smf[g2 * 32 + threadIdx.x];
        atomicAdd(&g_colsum[threadIdx.x], t);
    }
}
__global__ void finalize_k(const float* __restrict__ discW) {
    __shared__ float c[HH2];
    int t = threadIdx.x;
    float m = g_colsum[t] / (float)NN;
    c[t] = 1.f / (1.f + expf(-m));
    __syncwarp();
    float v = 0.f;
    #pragma unroll
    for (int k = 0; k < HH2; k++) v += discW[t * HH2 + k] * c[k];
    g_v[t] = v;
}
__global__ void ret_k(const float* __restrict__ dbp, float* __restrict__ out) {
    int n = blockIdx.x * blockDim.x + threadIdx.x;
    if (n >= NN) return;
    float db = dbp[0];
    float d0 = 0.f, d1 = 0.f, d2 = 0.f;
    float* xo_out = out + OUT_X2O + (size_t)n * HH2;
    #pragma unroll
    for (int k = 0; k < HH2; k += 4) {
        float4 v4 = *reinterpret_cast<const float4*>(&g_v[k]);
        float4 a  = *reinterpret_cast<const float4*>(&g_x2o[n * HH2 + k]);
        float4 b  = *reinterpret_cast<const float4*>(&g_x2oa[n * HH2 + k]);
        float4 c  = *reinterpret_cast<const float4*>(&g_x2oaa[n * HH2 + k]);
        d0 += a.x*v4.x + a.y*v4.y + a.z*v4.z + a.w*v4.w;
        d1 += b.x*v4.x + b.y*v4.y + b.z*v4.z + b.w*v4.w;
        d2 += c.x*v4.x + c.y*v4.y + c.z*v4.z + c.w*v4.w;
        *reinterpret_cast<float4*>(&xo_out[k]) = a;
    }
    out[OUT_RETOS  + 2 * n]     = d0 + db;
    out[OUT_RETOS  + 2 * n + 1] = d1 + db;
    out[OUT_RETOSA + 2 * n]     = d0 + db;
    out[OUT_RETOSA + 2 * n + 1] = d2 + db;
}
__global__ void cls_k(const int* __restrict__ idx, const float* __restrict__ f1,
                      const float* __restrict__ clsW, const float* __restrict__ clsB,
                      const float* __restrict__ attt, float* __restrict__ out)
{
    __shared__ float z[448];
    int b = blockIdx.x, t = threadIdx.x;
    int i0 = idx[b], i1 = idx[BB + b];
    float a0 = attt[0], a1 = attt[1];
    for (int k = t; k < 448; k += 128) {
        float val;
        if      (k < 64)  val = a0 * g_h1O[(size_t)i0 * 64 + k];
        else if (k < 96)  val = a1 * g_x2o[(size_t)i0 * 32 + (k - 64)];
        else if (k < 224) val = f1[(size_t)i0 * 128 + (k - 96)];
        else if (k < 288) val = a0 * g_h1O[(size_t)i1 * 64 + (k - 224)];
        else if (k < 320) val = a1 * g_x2o[(size_t)i1 * 32 + (k - 288)];
        else              val = f1[(size_t)i1 * 128 + (k - 320)];
        z[k] = val;
    }
    __syncthreads();
    if (t < RR) {
        float acc = clsB[t];
        #pragma unroll 4
        for (int k = 0; k < 448; k++) acc += z[k] * clsW[k * RR + t];
        out[(size_t)b * RR + t] = acc;
    }
}

// ---------------- launcher ------------------------------------------------------
extern "C" void kernel_launch(void* const* d_in, const int* in_sizes, int n_in,
                              void* d_out, int out_size)
{
    (void)in_sizes; (void)n_in; (void)out_size;
    const float* x_o   = (const float*)d_in[0];
    const float* x_a   = (const float*)d_in[1];
    const float* f1    = (const float*)d_in[2];
    const float* W1    = (const float*)d_in[3];
    const float* root1 = (const float*)d_in[4];
    const float* b1    = (const float*)d_in[5];
    const float* W2    = (const float*)d_in[6];
    const float* root2 = (const float*)d_in[7];
    const float* b2    = (const float*)d_in[8];
    const float* attt  = (const float*)d_in[9];
    const float* discW = (const float*)d_in[10];
    const float* discb = (const float*)d_in[11];
    const float* clsW  = (const float*)d_in[12];
    const float* clsb  = (const float*)d_in[13];
    const int*   ei    = (const int*)d_in[14];
    const int*   et0   = (const int*)d_in[15];
    const int*   et1   = (const int*)d_in[16];
    const int*   idx   = (const int*)d_in[17];
    float* out = (float*)d_out;

    float *h1O, *h1A, *h1Aa, *x2o, *x2oa, *x2oaa;
    cudaGetSymbolAddress((void**)&h1O,   g_h1O);
    cudaGetSymbolAddress((void**)&h1A,   g_h1A);
    cudaGetSymbolAddress((void**)&h1Aa,  g_h1Aa);
    cudaGetSymbolAddress((void**)&x2o,   g_x2o);
    cudaGetSymbolAddress((void**)&x2oa,  g_x2oa);
    cudaGetSymbolAddress((void**)&x2oaa, g_x2oaa);

    int *boff0, *boff1;
    int2 *sd0, *sd1;
    float *sc0, *sc1;
    cudaGetSymbolAddress((void**)&boff0, g_boff0); cudaGetSymbolAddress((void**)&boff1, g_boff1);
    cudaGetSymbolAddress((void**)&sd0, g_sd0);     cudaGetSymbolAddress((void**)&sd1, g_sd1);
    cudaGetSymbolAddress((void**)&sc0, g_sc0);     cudaGetSymbolAddress((void**)&sc1, g_sc1);

    __nv_bfloat16 *l1hi, *l1lo, *l2hi, *l2lo, *w1hi, *w1lo, *w2hi, *w2lo;
    cudaGetSymbolAddress((void**)&l1hi, g_l1hi); cudaGetSymbolAddress((void**)&l1lo, g_l1lo);
    cudaGetSymbolAddress((void**)&l2hi, g_l2hi); cudaGetSymbolAddress((void**)&l2lo, g_l2lo);
    cudaGetSymbolAddress((void**)&w1hi, g_w1hi); cudaGetSymbolAddress((void**)&w1lo, g_w1lo);
    cudaGetSymbolAddress((void**)&w2hi, g_w2hi); cudaGetSymbolAddress((void**)&w2lo, g_w2lo);

    const int SMP = 2 * 4 * 128 * 80;   // 81920 (>= 67584 Dsm)
    cudaFuncSetAttribute(gemm_fused<FIN, HH1>,
                         cudaFuncAttributeMaxDynamicSharedMemorySize, SMP);
    cudaFuncSetAttribute(gemm_fused<HH1, HH2>,
                         cudaFuncAttributeMaxDynamicSharedMemorySize, SMP);

    // ---- init + CSR build (tile buckets) ----
    init_k<<<(3 * NN * HH1 + 255) / 256, 256>>>(b1);
    count_k<<<(EE + 255) / 256, 256>>>(ei, et0, et1);
    bscan_k<<<2, 1024>>>();
    bfill_k<<<(EE + 255) / 256, 256>>>(ei, et0, et1);

    // ---- conversions ----
    convX2_k<<<(2 * SEG1 * FIN + 255) / 256, 256>>>(x_o, x_a);
    convW_k<FIN, HH1, RCP1><<<(RCP1 * FIN + 255) / 256, 256>>>(W1, root1, w1hi, w1lo);
    convW_k<HH1, HH2, RCP2><<<(RCP2 * HH1 + 255) / 256, 256>>>(W2, root2, w2hi, w2lo);

    // ---- layer 1: one fused launch (GEMM + root + scatter) ----
    {
        ScatAll P = {};
        P.off[0][0] = boff0; P.sd[0][0] = sd0; P.sc[0][0] = sc0; P.out[0][0] = h1O;
        P.off[0][1] = boff1; P.sd[0][1] = sd1; P.sc[0][1] = sc1; P.out[0][1] = h1Aa;
        P.off[1][0] = boff0; P.sd[1][0] = sd0; P.sc[1][0] = sc0; P.out[1][0] = h1A;
        gemm_fused<FIN, HH1><<<dim3(2 * NTILE, RCP1 / 128), 256, SMP>>>(
            l1hi, l1lo, w1hi, w1lo, P);
    }

    relu_conv_k<<<(3 * SEG1 * HH1 + 255) / 256, 256>>>(b2);

    // ---- layer 2: one fused launch ----
    {
        ScatAll P = {};
        P.off[0][0] = boff0; P.sd[0][0] = sd0; P.sc[0][0] = sc0; P.out[0][0] = x2o;
        P.off[1][0] = boff0; P.sd[1][0] = sd0; P.sc[1][0] = sc0; P.out[1][0] = x2oa;
        P.off[2][0] = boff1; P.sd[2][0] = sd1; P.sc[2][0] = sc1; P.out[2][0] = x2oaa;
        gemm_fused<HH1, HH2><<<dim3(3 * NTILE, RCP2 / 128), 256, SMP>>>(
            l2hi, l2lo, w2hi, w2lo, P);
    }

    // ---- readout / outputs ----
    colsum_k<<<80, 256>>>();
    finalize_k<<<1, 32>>>(discW);
    ret_k<<<(NN + 127) / 128, 128>>>(discb, out);
    cls_k<<<BB, 128>>>(idx, f1, clsW, clsb, attt, out);
}

// round 8
// speedup vs baseline: 1.1117x; 1.0463x over previous
#include <cuda_runtime.h>
#include <cuda_bf16.h>
#include <cstdint>

#define NN 20000
#define EE 640000
#define RR 65
#define FIN 128
#define HH1 64
#define HH2 32
#define BB 8192
#define SEG1 20096               /* 157*128 padded segment rows */
#define NTILE 157
#define NB (RR * NTILE)          /* 10205 tile buckets */
#define KEYS (RR * NN)
#define RCP1 4224                /* 66*64: rel 65 = root1 */
#define RCP2 2176                /* 68*32: rel 65 = root2, 66-67 zero */

#define OUT_RETOS  (BB*RR)
#define OUT_RETOSA (OUT_RETOS + 2*NN)
#define OUT_X2O    (OUT_RETOSA + 2*NN)

// conversion job flat ranges
#define CV_X   (2 * SEG1 * FIN)          /* 5,144,576 */
#define CV_W1  (RCP1 * FIN)              /* 540,672  */
#define CV_W2  (RCP2 * HH1)              /* 139,264  */
#define CV_TOT (CV_X + CV_W1 + CV_W2)

// ---------------- scratch ------------------------------------------------------
__device__ float g_h1O[NN * HH1];
__device__ float g_h1A[NN * HH1];
__device__ float g_h1Aa[NN * HH1];
__device__ float g_x2o[NN * HH2];
__device__ float g_x2oa[NN * HH2];
__device__ float g_x2oaa[NN * HH2];
__device__ int   g_cnt0[KEYS];
__device__ int   g_cnt1[KEYS];
__device__ __align__(16) float g_colsum[HH2];
__device__ __align__(16) float g_v[HH2];

// tile-bucket CSR: key = r*NTILE + (src>>7); record = {src, dst, scale_bits, 0}
__device__ int  g_bh0[NB], g_bh1[NB];
__device__ int  g_boff0[NB + 1], g_boff1[NB + 1];
__device__ int  g_bcur0[NB], g_bcur1[NB];
__device__ int4 g_ed0[EE], g_ed1[EE];

// packed bf16 hi/lo operands (segment-strided)
__device__ __nv_bfloat16 g_l1hi[2 * SEG1 * FIN], g_l1lo[2 * SEG1 * FIN];
__device__ __nv_bfloat16 g_l2hi[3 * SEG1 * HH1], g_l2lo[3 * SEG1 * HH1];
__device__ __nv_bfloat16 g_w1hi[RCP1 * FIN], g_w1lo[RCP1 * FIN];
__device__ __nv_bfloat16 g_w2hi[RCP2 * HH1], g_w2lo[RCP2 * HH1];

// ---------------- helpers ------------------------------------------------------
__device__ __forceinline__ uint32_t smem_u32(const void* p) {
    uint32_t a;
    asm("{ .reg .u64 t; cvta.to.shared.u64 t, %1; cvt.u32.u64 %0, t; }" : "=r"(a) : "l"(p));
    return a;
}
__device__ __forceinline__ void cp16(uint32_t dst, const void* src) {
    asm volatile("cp.async.cg.shared.global [%0], [%1], 16;"
                 :: "r"(dst), "l"(src) : "memory");
}
__device__ __forceinline__ void mma16816(float* d, const uint32_t* a, const uint32_t* b) {
    asm volatile("mma.sync.aligned.m16n8k16.row.col.f32.bf16.bf16.f32 "
        "{%0,%1,%2,%3}, {%4,%5,%6,%7}, {%8,%9}, {%0,%1,%2,%3};"
        : "+f"(d[0]), "+f"(d[1]), "+f"(d[2]), "+f"(d[3])
        : "r"(a[0]), "r"(a[1]), "r"(a[2]), "r"(a[3]), "r"(b[0]), "r"(b[1]));
}
#define LDSM4(R0,R1,R2,R3,addr) \
    asm volatile("ldmatrix.sync.aligned.m8n8.x4.shared.b16 {%0,%1,%2,%3}, [%4];" \
        : "=r"(R0), "=r"(R1), "=r"(R2), "=r"(R3) : "r"(addr))

struct ScatAll {
    const int*  off[3][2];
    const int4* ed[3][2];
    float*      out[3][2];
};

// ---------------- fused GEMM + scatter + root (segmented) ----------------------
template<int K, int H>
__global__ void __launch_bounds__(256, 2)
gemm_fused(const __nv_bfloat16* __restrict__ Ahi_g, const __nv_bfloat16* __restrict__ Alo_g,
           const __nv_bfloat16* __restrict__ Bhi_g, const __nv_bfloat16* __restrict__ Blo_g,
           ScatAll P)
{
    constexpr int KC = 32, NC = K / KC;
    constexpr int TILE_B = 128 * 80;       // 128 rows x 80B padded (40 bf16)
    extern __shared__ __align__(16) char sm[];

    const int tid = threadIdx.x;
    const int wid = tid >> 5, lane = tid & 31;
    const int gid = lane >> 2, tig = lane & 3;
    const int wm = wid & 1, wn = wid >> 1;
    const int m0 = blockIdx.x * 128;       // global packed row
    const int n0 = blockIdx.y * 128;
    const uint32_t smu = smem_u32(sm);

    const int seg = m0 / SEG1;
    const int mloc = m0 - seg * SEG1;
    const int tile = mloc >> 7;
    const int r_base = n0 / H;

    float acc[4][4][4] = {};

    uint32_t a_off[4], b_off[2];
    #pragma unroll
    for (int mt = 0; mt < 4; mt++)
        a_off[mt] = (uint32_t)((wm * 64 + mt * 16 + (lane & 15)) * 80 + ((lane & 16) ? 16 : 0));
    #pragma unroll
    for (int p = 0; p < 2; p++)
        b_off[p] = (uint32_t)((wn * 32 + p * 16 + (lane & 7) + ((lane & 16) ? 8 : 0)) * 80
                              + ((lane & 8) ? 16 : 0));

    auto load_chunk = [&](int c, int s) {
        const int koff = c * KC;
        const uint32_t st = smu + s * (4 * TILE_B);
        const __nv_bfloat16* srcs[4] = { Ahi_g, Alo_g, Bhi_g, Blo_g };
        #pragma unroll
        for (int j = 0; j < 8; j++) {
            int i = tid + j * 256;
            int t = i >> 9;
            int row = (i >> 2) & 127;
            int ch = i & 3;
            int rg = (t < 2 ? m0 : n0) + row;
            cp16(st + t * TILE_B + row * 80 + ch * 16,
                 srcs[t] + (size_t)rg * K + koff + ch * 8);
        }
        asm volatile("cp.async.commit_group;" ::: "memory");
    };

    auto compute = [&](int s) {
        const uint32_t base = smu + s * (4 * TILE_B);
        #pragma unroll
        for (int ks = 0; ks < 2; ks++) {
            const uint32_t kb = ks * 32;
            uint32_t ah[4][4], al[4][4], bh[4][2], bl[4][2];
            #pragma unroll
            for (int mt = 0; mt < 4; mt++) {
                LDSM4(ah[mt][0], ah[mt][1], ah[mt][2], ah[mt][3], base + a_off[mt] + kb);
                LDSM4(al[mt][0], al[mt][1], al[mt][2], al[mt][3], base + TILE_B + a_off[mt] + kb);
            }
            #pragma unroll
            for (int p = 0; p < 2; p++) {
                LDSM4(bh[2*p][0], bh[2*p][1], bh[2*p+1][0], bh[2*p+1][1],
                      base + 2 * TILE_B + b_off[p] + kb);
                LDSM4(bl[2*p][0], bl[2*p][1], bl[2*p+1][0], bl[2*p+1][1],
                      base + 3 * TILE_B + b_off[p] + kb);
            }
            #pragma unroll
            for (int mt = 0; mt < 4; mt++)
                #pragma unroll
                for (int nt = 0; nt < 4; nt++) {
                    mma16816(acc[mt][nt], ah[mt], bh[nt]);
                    mma16816(acc[mt][nt], ah[mt], bl[nt]);
                    mma16816(acc[mt][nt], al[mt], bh[nt]);
                }
        }
    };

    load_chunk(0, 0);
    #pragma unroll
    for (int c = 0; c < NC; c++) {
        if (c + 1 < NC) {
            load_chunk(c + 1, (c + 1) & 1);
            asm volatile("cp.async.wait_group 1;" ::: "memory");
        } else {
            asm volatile("cp.async.wait_group 0;" ::: "memory");
        }
        __syncthreads();
        compute(c & 1);
        __syncthreads();
    }

    // ---- prefetch bucket ranges (overlap L2 latency with Dsm staging) ----
    int e_lo[2][128 / H], e_hi[2][128 / H];
    #pragma unroll
    for (int pq = 0; pq < 2; pq++)
        if (P.out[seg][pq]) {
            #pragma unroll
            for (int ri = 0; ri < 128 / H; ri++) {
                int r = r_base + ri;
                if (r < RR) {
                    int b = r * NTILE + tile;
                    e_lo[pq][ri] = __ldg(&P.off[seg][pq][b]);
                    e_hi[pq][ri] = __ldg(&P.off[seg][pq][b + 1]);
                } else { e_lo[pq][ri] = 0; e_hi[pq][ri] = 0; }
            }
        }

    // ---- stage tile to SMEM ----
    float* Dsm = reinterpret_cast<float*>(sm);
    #pragma unroll
    for (int mt = 0; mt < 4; mt++) {
        int r = wm * 64 + mt * 16 + gid;
        #pragma unroll
        for (int nt = 0; nt < 4; nt++) {
            int c = wn * 32 + nt * 8 + tig * 2;
            *reinterpret_cast<float2*>(Dsm + r * 132 + c) =
                make_float2(acc[mt][nt][0], acc[mt][nt][1]);
            *reinterpret_cast<float2*>(Dsm + (r + 8) * 132 + c) =
                make_float2(acc[mt][nt][2], acc[mt][nt][3]);
        }
    }
    __syncthreads();

    // ---- scatter: CSR edges for real relations, dense add for phantom root ----
    constexpr int TPE = H / 4;
    constexpr int NSUB = 256 / TPE;
    const int sub = tid / TPE, q = tid % TPE;
    const int end_src = (mloc + 128 <= NN) ? 128 : (NN - mloc);

    #pragma unroll
    for (int pq = 0; pq < 2; pq++) {
        float* outp = P.out[seg][pq];
        if (!outp) continue;
        const int4* ed = P.ed[seg][pq];
        #pragma unroll
        for (int ri = 0; ri < 128 / H; ri++) {
            int r = r_base + ri;
            if (r < RR) {
                for (int e = e_lo[pq][ri] + sub; e < e_hi[pq][ri]; e += NSUB) {
                    int4 rec = __ldg(&ed[e]);
                    float scale = __int_as_float(rec.z);
                    const float* p = Dsm + (rec.x - mloc) * 132 + ri * H + q * 4;
                    float4 v = *reinterpret_cast<const float4*>(p);
                    float4 w = make_float4(v.x * scale, v.y * scale, v.z * scale, v.w * scale);
                    atomicAdd(reinterpret_cast<float4*>(outp + (size_t)rec.y * H + q * 4), w);
                }
            } else if (r == RR) {                  // phantom root relation
                for (int row = sub; row < end_src; row += NSUB) {
                    const float* p = Dsm + row * 132 + ri * H + q * 4;
                    float4 v = *reinterpret_cast<const float4*>(p);
                    atomicAdd(reinterpret_cast<float4*>(outp + (size_t)(mloc + row) * H + q * 4), v);
                }
            }
        }
    }
}

// ---------------- CSR build ----------------------------------------------------
__global__ void init_k(const float* __restrict__ b1) {
    int i = blockIdx.x * blockDim.x + threadIdx.x;
    if (i < KEYS) { g_cnt0[i] = 0; g_cnt1[i] = 0; }
    if (i < NB) { g_bh0[i] = 0; g_bh1[i] = 0; }
    if (i < HH2) g_colsum[i] = 0.f;
    if (i < 3 * NN * HH1) {
        int seg = i / (NN * HH1);
        int j = i - seg * (NN * HH1);
        float v = b1[j & (HH1 - 1)];
        ((seg == 0) ? g_h1O : (seg == 1) ? g_h1A : g_h1Aa)[j] = v;
    }
}
__global__ void count_k(const int* __restrict__ ei, const int* __restrict__ et0,
                        const int* __restrict__ et1) {
    int e = blockIdx.x * blockDim.x + threadIdx.x;
    if (e >= EE) return;
    int s = ei[e], d = ei[EE + e];
    int r0 = et0[e], r1 = et1[e];
    atomicAdd(&g_cnt0[r0 * NN + d], 1);
    atomicAdd(&g_cnt1[r1 * NN + d], 1);
    atomicAdd(&g_bh0[r0 * NTILE + (s >> 7)], 1);
    atomicAdd(&g_bh1[r1 * NTILE + (s >> 7)], 1);
}
__global__ void bscan_k() {
    __shared__ int smi[1024];
    __shared__ int run;
    const int* hist = blockIdx.x ? g_bh1 : g_bh0;
    int* off = blockIdx.x ? g_boff1 : g_boff0;
    int* cur = blockIdx.x ? g_bcur1 : g_bcur0;
    int t = threadIdx.x;
    if (t == 0) run = 0;
    __syncthreads();
    for (int base = 0; base < NB; base += 1024) {
        int i = base + t;
        int v = (i < NB) ? hist[i] : 0;
        smi[t] = v;
        __syncthreads();
        for (int o = 1; o < 1024; o <<= 1) {
            int x = (t >= o) ? smi[t - o] : 0;
            __syncthreads();
            smi[t] += x;
            __syncthreads();
        }
        int r = run;
        if (i < NB) { int excl = smi[t] - v + r; off[i] = excl; cur[i] = excl; }
        __syncthreads();
        if (t == 1023) run = r + smi[1023];
        __syncthreads();
    }
    if (t == 0) off[NB] = EE;
}
__global__ void bfill_k(const int* __restrict__ ei, const int* __restrict__ et0,
                        const int* __restrict__ et1) {
    int e = blockIdx.x * blockDim.x + threadIdx.x;
    if (e >= EE) return;
    int s = ei[e], d = ei[EE + e];
    {
        int r = et0[e];
        float sc = 1.f / (float)max(__ldg(&g_cnt0[r * NN + d]), 1);
        int p = atomicAdd(&g_bcur0[r * NTILE + (s >> 7)], 1);
        g_ed0[p] = make_int4(s, d, __float_as_int(sc), 0);
    }
    {
        int r = et1[e];
        float sc = 1.f / (float)max(__ldg(&g_cnt1[r * NN + d]), 1);
        int p = atomicAdd(&g_bcur1[r * NTILE + (s >> 7)], 1);
        g_ed1[p] = make_int4(s, d, __float_as_int(sc), 0);
    }
}

// ---------------- merged conversions -------------------------------------------
__global__ void convAll_k(const float* __restrict__ x_o, const float* __restrict__ x_a,
                          const float* __restrict__ W1, const float* __restrict__ root1,
                          const float* __restrict__ W2, const float* __restrict__ root2)
{
    int i = blockIdx.x * blockDim.x + threadIdx.x;
    if (i >= CV_TOT) return;
    float v;
    __nv_bfloat16 *hi, *lo;
    int j;
    if (i < CV_X) {
        j = i;
        int seg = j / (SEG1 * FIN);
        int jj = j - seg * (SEG1 * FIN);
        int row = jj / FIN, col = jj - row * FIN;
        v = (row < NN) ? (seg ? x_a : x_o)[row * FIN + col] : 0.f;
        hi = g_l1hi; lo = g_l1lo;
    } else if (i < CV_X + CV_W1) {
        j = i - CV_X;
        int c = j / FIN, k = j - c * FIN;
        int r = c / HH1;
        v = (r < RR) ? W1[(size_t)r * (FIN * HH1) + (size_t)k * HH1 + (c % HH1)]
          : (r == RR) ? root1[(size_t)k * HH1 + (c % HH1)] : 0.f;
        hi = g_w1hi; lo = g_w1lo;
    } else {
        j = i - CV_X - CV_W1;
        int c = j / HH1, k = j - c * HH1;
        int r = c / HH2;
        v = (r < RR) ? W2[(size_t)r * (HH1 * HH2) + (size_t)k * HH2 + (c % HH2)]
          : (r == RR) ? root2[(size_t)k * HH2 + (c % HH2)] : 0.f;
        hi = g_w2hi; lo = g_w2lo;
    }
    __nv_bfloat16 h = __float2bfloat16_rn(v);
    hi[j] = h;
    lo[j] = __float2bfloat16_rn(v - __bfloat162float(h));
}
__global__ void relu_conv_k(const float* __restrict__ b2) {
    int i = blockIdx.x * blockDim.x + threadIdx.x;
    if (i < 3 * SEG1 * HH1) {
        int seg = i / (SEG1 * HH1);
        int j = i - seg * (SEG1 * HH1);
        int row = j / HH1, col = j - row * HH1;
        float v = 0.f;
        if (row < NN) {
            float* arr = (seg == 0) ? g_h1O : (seg == 1) ? g_h1A : g_h1Aa;
            v = fmaxf(arr[row * HH1 + col], 0.f);
            arr[row * HH1 + col] = v;
        }
        __nv_bfloat16 h = __float2bfloat16_rn(v);
        g_l2hi[i] = h;
        g_l2lo[i] = __float2bfloat16_rn(v - __bfloat162float(h));
    }
    if (i < 3 * NN * HH2) {
        int seg = i / (NN * HH2);
        int j = i - seg * (NN * HH2);
        ((seg == 0) ? g_x2o : (seg == 1) ? g_x2oa : g_x2oaa)[j] = b2[j & (HH2 - 1)];
    }
}

// ---------------- readout / discriminator --------------------------------------
__global__ void colsum_k() {
    __shared__ float smf[256];
    int col = threadIdx.x & 31, grp = threadIdx.x >> 5;
    float s = 0.f;
    for (int n = blockIdx.x * 8 + grp; n < NN; n += gridDim.x * 8)
        s += g_x2o[n * HH2 + col];
    smf[threadIdx.x] = s;
    __syncthreads();
    if (threadIdx.x < 32) {
        float t = 0.f;
        #pragma unroll
        for (int g2 = 0; g2 < 8; g2++) t += smf[g2 * 32 + threadIdx.x];
        atomicAdd(&g_colsum[threadIdx.x], t);
    }
}
__global__ void finalize_k(const float* __restrict__ discW) {
    __shared__ float c[HH2];
    int t = threadIdx.x;
    float m = g_colsum[t] / (float)NN;
    c[t] = 1.f / (1.f + expf(-m));
    __syncwarp();
    float v = 0.f;
    #pragma unroll
    for (int k = 0; k < HH2; k++) v += discW[t * HH2 + k] * c[k];
    g_v[t] = v;
}
__global__ void ret_k(const float* __restrict__ dbp, float* __restrict__ out) {
    int n = blockIdx.x * blockDim.x + threadIdx.x;
    if (n >= NN) return;
    float db = dbp[0];
    float d0 = 0.f, d1 = 0.f, d2 = 0.f;
    float* xo_out = out + OUT_X2O + (size_t)n * HH2;
    #pragma unroll
    for (int k = 0; k < HH2; k += 4) {
        float4 v4 = *reinterpret_cast<const float4*>(&g_v[k]);
        float4 a  = *reinterpret_cast<const float4*>(&g_x2o[n * HH2 + k]);
        float4 b  = *reinterpret_cast<const float4*>(&g_x2oa[n * HH2 + k]);
        float4 c  = *reinterpret_cast<const float4*>(&g_x2oaa[n * HH2 + k]);
        d0 += a.x*v4.x + a.y*v4.y + a.z*v4.z + a.w*v4.w;
        d1 += b.x*v4.x + b.y*v4.y + b.z*v4.z + b.w*v4.w;
        d2 += c.x*v4.x + c.y*v4.y + c.z*v4.z + c.w*v4.w;
        *reinterpret_cast<float4*>(&xo_out[k]) = a;
    }
    out[OUT_RETOS  + 2 * n]     = d0 + db;
    out[OUT_RETOS  + 2 * n + 1] = d1 + db;
    out[OUT_RETOSA + 2 * n]     = d0 + db;
    out[OUT_RETOSA + 2 * n + 1] = d2 + db;
}
__global__ void cls_k(const int* __restrict__ idx, const float* __restrict__ f1,
                      const float* __restrict__ clsW, const float* __restrict__ clsB,
                      const float* __restrict__ attt, float* __restrict__ out)
{
    __shared__ float z[448];
    int b = blockIdx.x, t = threadIdx.x;
    int i0 = idx[b], i1 = idx[BB + b];
    float a0 = attt[0], a1 = attt[1];
    for (int k = t; k < 448; k += 128) {
        float val;
        if      (k < 64)  val = a0 * g_h1O[(size_t)i0 * 64 + k];
        else if (k < 96)  val = a1 * g_x2o[(size_t)i0 * 32 + (k - 64)];
        else if (k < 224) val = f1[(size_t)i0 * 128 + (k - 96)];
        else if (k < 288) val = a0 * g_h1O[(size_t)i1 * 64 + (k - 224)];
        else if (k < 320) val = a1 * g_x2o[(size_t)i1 * 32 + (k - 288)];
        else              val = f1[(size_t)i1 * 128 + (k - 320)];
        z[k] = val;
    }
    __syncthreads();
    if (t < RR) {
        float acc = clsB[t];
        #pragma unroll 4
        for (int k = 0; k < 448; k++) acc += z[k] * clsW[k * RR + t];
        out[(size_t)b * RR + t] = acc;
    }
}

// ---------------- launcher ------------------------------------------------------
extern "C" void kernel_launch(void* const* d_in, const int* in_sizes, int n_in,
                              void* d_out, int out_size)
{
    (void)in_sizes; (void)n_in; (void)out_size;
    const float* x_o   = (const float*)d_in[0];
    const float* x_a   = (const float*)d_in[1];
    const float* f1    = (const float*)d_in[2];
    const float* W1    = (const float*)d_in[3];
    const float* root1 = (const float*)d_in[4];
    const float* b1    = (const float*)d_in[5];
    const float* W2    = (const float*)d_in[6];
    const float* root2 = (const float*)d_in[7];
    const float* b2    = (const float*)d_in[8];
    const float* attt  = (const float*)d_in[9];
    const float* discW = (const float*)d_in[10];
    const float* discb = (const float*)d_in[11];
    const float* clsW  = (const float*)d_in[12];
    const float* clsb  = (const float*)d_in[13];
    const int*   ei    = (const int*)d_in[14];
    const int*   et0   = (const int*)d_in[15];
    const int*   et1   = (const int*)d_in[16];
    const int*   idx   = (const int*)d_in[17];
    float* out = (float*)d_out;

    float *h1O, *h1A, *h1Aa, *x2o, *x2oa, *x2oaa;
    cudaGetSymbolAddress((void**)&h1O,   g_h1O);
    cudaGetSymbolAddress((void**)&h1A,   g_h1A);
    cudaGetSymbolAddress((void**)&h1Aa,  g_h1Aa);
    cudaGetSymbolAddress((void**)&x2o,   g_x2o);
    cudaGetSymbolAddress((void**)&x2oa,  g_x2oa);
    cudaGetSymbolAddress((void**)&x2oaa, g_x2oaa);

    int *boff0, *boff1;
    int4 *ed0, *ed1;
    cudaGetSymbolAddress((void**)&boff0, g_boff0); cudaGetSymbolAddress((void**)&boff1, g_boff1);
    cudaGetSymbolAddress((void**)&ed0, g_ed0);     cudaGetSymbolAddress((void**)&ed1, g_ed1);

    __nv_bfloat16 *l1hi, *l1lo, *l2hi, *l2lo, *w1hi, *w1lo, *w2hi, *w2lo;
    cudaGetSymbolAddress((void**)&l1hi, g_l1hi); cudaGetSymbolAddress((void**)&l1lo, g_l1lo);
    cudaGetSymbolAddress((void**)&l2hi, g_l2hi); cudaGetSymbolAddress((void**)&l2lo, g_l2lo);
    cudaGetSymbolAddress((void**)&w1hi, g_w1hi); cudaGetSymbolAddress((void**)&w1lo, g_w1lo);
    cudaGetSymbolAddress((void**)&w2hi, g_w2hi); cudaGetSymbolAddress((void**)&w2lo, g_w2lo);

    const int SMP = 2 * 4 * 128 * 80;   // 81920 (>= 67584 Dsm)
    cudaFuncSetAttribute(gemm_fused<FIN, HH1>,
                         cudaFuncAttributeMaxDynamicSharedMemorySize, SMP);
    cudaFuncSetAttribute(gemm_fused<HH1, HH2>,
                         cudaFuncAttributeMaxDynamicSharedMemorySize, SMP);

    // ---- launches 1-5: init, CSR build, conversions ----
    init_k<<<(3 * NN * HH1 + 255) / 256, 256>>>(b1);
    count_k<<<(EE + 255) / 256, 256>>>(ei, et0, et1);
    bscan_k<<<2, 1024>>>();
    bfill_k<<<(EE + 255) / 256, 256>>>(ei, et0, et1);
    convAll_k<<<(CV_TOT + 255) / 256, 256>>>(x_o, x_a, W1, root1, W2, root2);

    // ---- launch 6: layer-1 fused (GEMM + root + scatter) — ncu target ----
    {
        ScatAll P = {};
        P.off[0][0] = boff0; P.ed[0][0] = ed0; P.out[0][0] = h1O;
        P.off[0][1] = boff1; P.ed[0][1] = ed1; P.out[0][1] = h1Aa;
        P.off[1][0] = boff0; P.ed[1][0] = ed0; P.out[1][0] = h1A;
        gemm_fused<FIN, HH1><<<dim3(2 * NTILE, RCP1 / 128), 256, SMP>>>(
            l1hi, l1lo, w1hi, w1lo, P);
    }

    relu_conv_k<<<(3 * SEG1 * HH1 + 255) / 256, 256>>>(b2);

    // ---- layer 2: one fused launch ----
    {
        ScatAll P = {};
        P.off[0][0] = boff0; P.ed[0][0] = ed0; P.out[0][0] = x2o;
        P.off[1][0] = boff0; P.ed[1][0] = ed0; P.out[1][0] = x2oa;
        P.off[2][0] = boff1; P.ed[2][0] = ed1; P.out[2][0] = x2oaa;
        gemm_fused<HH1, HH2><<<dim3(3 * NTILE, RCP2 / 128), 256, SMP>>>(
            l2hi, l2lo, w2hi, w2lo, P);
    }

    // ---- readout / outputs ----
    colsum_k<<<80, 256>>>();
    finalize_k<<<1, 32>>>(discW);
    ret_k<<<(NN + 127) / 128, 128>>>(discb, out);
    cls_k<<<BB, 128>>>(idx, f1, clsW, clsb, attt, out);
}